// round 16
// baseline (speedup 1.0000x reference)
#include <cuda_runtime.h>
#include <cuda_bf16.h>
#include <cuda_fp16.h>
#include <mma.h>
#include <cstdint>

using namespace nvcuda;

#define NNODES 100000
#define EMAX   1600000
#define KDIM   128
#define SCAN_B 1024

// ---------------- scratch (no allocation allowed) ----------------
__device__ __align__(16) float g_dinv[NNODES];
__device__            int   g_deg[NNODES];
__device__            int   g_off[NNODES + 1];
__device__            int   g_cur[NNODES];
__device__            int   g_srcl[EMAX];
__device__            int   g_bsum[128];
__device__            int   g_bpre[128];
__device__ __align__(16) __half g_xh[(size_t)NNODES * 128];     // x in fp16
__device__ __align__(16) __half g_tmp1h[(size_t)NNODES * 128];  // GEMM out, fp16 (L1: unscaled h; L2: dinv*h2)
__device__ __align__(16) __half g_hacth[(size_t)NNODES * 128];  // relu(layer1) fp16 = GEMM2's A

// ---------------- x -> fp16 conversion (pure streaming, no deps) ----------
__global__ void convert_x_kernel(const float* __restrict__ x, int total8) {
    int i = blockIdx.x * blockDim.x + threadIdx.x;
    if (i < total8) {
        float4 v0 = *(const float4*)(x + (size_t)i * 8);
        float4 v1 = *(const float4*)(x + (size_t)i * 8 + 4);
        __half2 p0 = __floats2half2_rn(v0.x, v0.y);
        __half2 p1 = __floats2half2_rn(v0.z, v0.w);
        __half2 p2 = __floats2half2_rn(v1.x, v1.y);
        __half2 p3 = __floats2half2_rn(v1.z, v1.w);
        uint4 u;
        u.x = *(unsigned*)&p0; u.y = *(unsigned*)&p1;
        u.z = *(unsigned*)&p2; u.w = *(unsigned*)&p3;
        ((uint4*)g_xh)[i] = u;
    }
}

// ---------------- degree ----------------
__global__ void deg_init_kernel(int n) {
    int i = blockIdx.x * blockDim.x + threadIdx.x;
    if (i < n) g_deg[i] = 0;
}
__global__ void deg_count_kernel(const int* __restrict__ dst, int E) {
    int i4 = blockIdx.x * blockDim.x + threadIdx.x;
    int i = i4 * 4;
    if (i + 4 <= E) {
        int4 d = *(const int4*)(dst + i);
        atomicAdd(&g_deg[d.x], 1);
        atomicAdd(&g_deg[d.y], 1);
        atomicAdd(&g_deg[d.z], 1);
        atomicAdd(&g_deg[d.w], 1);
    } else {
        for (; i < E; i++) atomicAdd(&g_deg[dst[i]], 1);
    }
}
__global__ void dinv_kernel(int n) {
    int i = blockIdx.x * blockDim.x + threadIdx.x;
    if (i < n) g_dinv[i] = rsqrtf((float)g_deg[i] + 1.0f);   // +1 self loop
}

// ---------------- multi-block exclusive scan ----------------
__global__ __launch_bounds__(SCAN_B) void scan1_kernel(int n) {
    __shared__ int sp[SCAN_B];
    int t = threadIdx.x;
    int i = blockIdx.x * SCAN_B + t;
    int d = (i < n) ? g_deg[i] : 0;
    sp[t] = d;
    __syncthreads();
#pragma unroll
    for (int off = 1; off < SCAN_B; off <<= 1) {
        int v = (t >= off) ? sp[t - off] : 0;
        __syncthreads();
        sp[t] += v;
        __syncthreads();
    }
    if (i < n) g_off[i] = sp[t] - d;
    if (t == SCAN_B - 1) g_bsum[blockIdx.x] = sp[t];
}
__global__ void scan2_kernel(int nb, int n) {
    __shared__ int sp[128];
    int t = threadIdx.x;
    int v = (t < nb) ? g_bsum[t] : 0;
    sp[t] = v;
    __syncthreads();
#pragma unroll
    for (int off = 1; off < 128; off <<= 1) {
        int u = (t >= off) ? sp[t - off] : 0;
        __syncthreads();
        sp[t] += u;
        __syncthreads();
    }
    if (t < nb) g_bpre[t] = sp[t] - v;
    if (t == nb - 1) g_off[n] = sp[t];
}
__global__ __launch_bounds__(SCAN_B) void scan3_kernel(int n) {
    int i = blockIdx.x * SCAN_B + threadIdx.x;
    if (i < n) {
        g_off[i] += g_bpre[blockIdx.x];
        g_cur[i] = 0;
    }
}

// ---------------- CSR fill ----------------
__global__ void fill_kernel(const int* __restrict__ src,
                            const int* __restrict__ dst, int E) {
    int i = blockIdx.x * blockDim.x + threadIdx.x;
    if (i < E) {
        int d = dst[i];
        int pos = atomicAdd(&g_cur[d], 1);
        g_srcl[g_off[d] + pos] = src[i];
    }
}

// ---------------- WMMA GEMM (512 threads), fp16 A, fp16 out ---------------
// SCALE: multiply epilogue by dinv[r] (layer 2); else store raw (layer 1).
// XSRC: A = g_xh else g_hacth — resolved DEVICE-side (never a host arg).
template<int BN, bool XSRC, bool SCALE>
__global__ __launch_bounds__(512) void wmma_gemm_kernel(
        const float* __restrict__ W, int M)
{
    constexpr int AS = 136;
    constexpr int BS = BN + 8;
    constexpr int CS = BN + 8;
    constexpr int NW = (BN == 128) ? 4 : 2;
    constexpr int MW = 16 / NW;
    constexpr int MI = 128 / (MW * 16);
    constexpr int NJ = BN / (NW * 16);
    extern __shared__ __half smh[];
    __half* Asm = smh;
    __half* Wsm = smh + 128 * AS;
    float*  Csm = (float*)smh;

    const __half* Ah = XSRC ? g_xh : g_hacth;

    int tid = threadIdx.x;
    int warp = tid >> 5;
    int wm = (warp / NW) * MI * 16;
    int wn = (warp % NW) * NJ * 16;
    int m0 = blockIdx.x * 128;

    for (int idx = tid; idx < 128 * 16; idx += 512) {
        int r = idx >> 4, c8 = (idx & 15) * 8;
        uint4 u = make_uint4(0u, 0u, 0u, 0u);
        if (m0 + r < M) u = *(const uint4*)(Ah + (size_t)(m0 + r) * 128 + c8);
        *(uint4*)(Asm + r * AS + c8) = u;
    }
    for (int idx = tid; idx < 128 * (BN / 4); idx += 512) {
        int r = idx / (BN / 4), c4 = (idx % (BN / 4)) * 4;
        float4 v = *(const float4*)(W + (size_t)r * BN + c4);
        __half2 p0 = __floats2half2_rn(v.x, v.y);
        __half2 p1 = __floats2half2_rn(v.z, v.w);
        uint2 u; u.x = *(unsigned*)&p0; u.y = *(unsigned*)&p1;
        *(uint2*)(Wsm + r * BS + c4) = u;
    }
    __syncthreads();

    wmma::fragment<wmma::accumulator, 16, 16, 16, float> c[MI][NJ];
#pragma unroll
    for (int i = 0; i < MI; i++)
#pragma unroll
        for (int j = 0; j < NJ; j++) wmma::fill_fragment(c[i][j], 0.0f);

#pragma unroll
    for (int k = 0; k < 128; k += 16) {
        wmma::fragment<wmma::matrix_a, 16, 16, 16, __half, wmma::row_major> a[MI];
#pragma unroll
        for (int i = 0; i < MI; i++)
            wmma::load_matrix_sync(a[i], Asm + (wm + i * 16) * AS + k, AS);
#pragma unroll
        for (int j = 0; j < NJ; j++) {
            wmma::fragment<wmma::matrix_b, 16, 16, 16, __half, wmma::row_major> b;
            wmma::load_matrix_sync(b, Wsm + k * BS + wn + j * 16, BS);
#pragma unroll
            for (int i = 0; i < MI; i++)
                wmma::mma_sync(c[i][j], a[i], b, c[i][j]);
        }
    }

    __syncthreads();
#pragma unroll
    for (int i = 0; i < MI; i++)
#pragma unroll
        for (int j = 0; j < NJ; j++)
            wmma::store_matrix_sync(Csm + (wm + i * 16) * CS + wn + j * 16,
                                    c[i][j], CS, wmma::mem_row_major);
    __syncthreads();

    for (int idx = tid; idx < 128 * (BN / 2); idx += 512) {
        int r = idx / (BN / 2), c2 = (idx % (BN / 2)) * 2;
        int gr = m0 + r;
        if (gr < M) {
            float s = SCALE ? g_dinv[gr] : 1.0f;
            float2 v = *(float2*)(Csm + r * CS + c2);
            __half2 h = __floats2half2_rn(v.x * s, v.y * s);
            *(unsigned*)(g_tmp1h + (size_t)gr * BN + c2) = *(unsigned*)&h;
        }
    }
}

// ---------------- gather aggregation ----------------
__device__ __forceinline__ void acc_u4(float* s, uint4 u) {
    __half2* h = (__half2*)&u;
#pragma unroll
    for (int i = 0; i < 4; i++) {
        float2 f = __half22float2(h[i]);
        s[2 * i]     += f.x;
        s[2 * i + 1] += f.y;
    }
}
__device__ __forceinline__ void acc_u4s(float* s, uint4 u, float w) {
    __half2* h = (__half2*)&u;
#pragma unroll
    for (int i = 0; i < 4; i++) {
        float2 f = __half22float2(h[i]);
        s[2 * i]     = fmaf(w, f.x, s[2 * i]);
        s[2 * i + 1] = fmaf(w, f.y, s[2 * i + 1]);
    }
}

// layer 1: 2 nodes per warp; rows UNSCALED -> apply dinv[s] per edge here
__global__ void agg1_kernel(const float* __restrict__ b1, int n) {
    int w = (int)((blockIdx.x * (unsigned)blockDim.x + threadIdx.x) >> 5);
    int lane = threadIdx.x & 31;
    int d = w * 2 + (lane >> 4);
    int hl = lane & 15;
    if (d >= n) return;
    const uint4* base = (const uint4*)g_tmp1h;
    float s[8] = {0, 0, 0, 0, 0, 0, 0, 0};
    float sc = g_dinv[d];
    acc_u4s(s, base[(size_t)d * 16 + hl], sc);      // self loop (dinv[d])
    int j = g_off[d], end = g_off[d + 1];
    for (; j + 4 <= end; j += 4) {
        int s0 = g_srcl[j], s1 = g_srcl[j + 1], s2 = g_srcl[j + 2], s3 = g_srcl[j + 3];
        float d0 = g_dinv[s0], d1 = g_dinv[s1], d2 = g_dinv[s2], d3 = g_dinv[s3];
        uint4 u0 = base[(size_t)s0 * 16 + hl];
        uint4 u1 = base[(size_t)s1 * 16 + hl];
        uint4 u2 = base[(size_t)s2 * 16 + hl];
        uint4 u3 = base[(size_t)s3 * 16 + hl];
        acc_u4s(s, u0, d0); acc_u4s(s, u1, d1);
        acc_u4s(s, u2, d2); acc_u4s(s, u3, d3);
    }
    for (; j < end; j++) {
        int sj = g_srcl[j];
        acc_u4s(s, base[(size_t)sj * 16 + hl], g_dinv[sj]);
    }
    float4 ba = ((const float4*)b1)[hl * 2];
    float4 bbv = ((const float4*)b1)[hl * 2 + 1];
    float o[8];
    o[0] = fmaxf(fmaf(sc, s[0], ba.x), 0.f);
    o[1] = fmaxf(fmaf(sc, s[1], ba.y), 0.f);
    o[2] = fmaxf(fmaf(sc, s[2], ba.z), 0.f);
    o[3] = fmaxf(fmaf(sc, s[3], ba.w), 0.f);
    o[4] = fmaxf(fmaf(sc, s[4], bbv.x), 0.f);
    o[5] = fmaxf(fmaf(sc, s[5], bbv.y), 0.f);
    o[6] = fmaxf(fmaf(sc, s[6], bbv.z), 0.f);
    o[7] = fmaxf(fmaf(sc, s[7], bbv.w), 0.f);
    __half2 p0 = __floats2half2_rn(o[0], o[1]);
    __half2 p1 = __floats2half2_rn(o[2], o[3]);
    __half2 p2 = __floats2half2_rn(o[4], o[5]);
    __half2 p3 = __floats2half2_rn(o[6], o[7]);
    uint4 u;
    u.x = *(unsigned*)&p0; u.y = *(unsigned*)&p1;
    u.z = *(unsigned*)&p2; u.w = *(unsigned*)&p3;
    ((uint4*)g_hacth)[(size_t)d * 16 + hl] = u;
}

// layer 2: 4 nodes per warp; rows pre-scaled (dinv in GEMM2 epilogue)
__global__ void agg2_kernel(const float* __restrict__ b2, float* __restrict__ out, int n) {
    int w = (int)((blockIdx.x * (unsigned)blockDim.x + threadIdx.x) >> 5);
    int lane = threadIdx.x & 31;
    int d = w * 4 + (lane >> 3);
    int hl = lane & 7;
    if (d >= n) return;
    const uint4* base = (const uint4*)g_tmp1h;
    float s[8] = {0, 0, 0, 0, 0, 0, 0, 0};
    acc_u4(s, base[(size_t)d * 8 + hl]);        // self loop
    int j = g_off[d], end = g_off[d + 1];
    for (; j + 4 <= end; j += 4) {
        int s0 = g_srcl[j], s1 = g_srcl[j + 1], s2 = g_srcl[j + 2], s3 = g_srcl[j + 3];
        uint4 u0 = base[(size_t)s0 * 8 + hl];
        uint4 u1 = base[(size_t)s1 * 8 + hl];
        uint4 u2 = base[(size_t)s2 * 8 + hl];
        uint4 u3 = base[(size_t)s3 * 8 + hl];
        acc_u4(s, u0); acc_u4(s, u1); acc_u4(s, u2); acc_u4(s, u3);
    }
    for (; j < end; j++) acc_u4(s, base[(size_t)g_srcl[j] * 8 + hl]);
    float sc = g_dinv[d];
    float4 ba = ((const float4*)b2)[hl * 2];
    float4 bbv = ((const float4*)b2)[hl * 2 + 1];
    float4 o0, o1;
    o0.x = fmaf(sc, s[0], ba.x);
    o0.y = fmaf(sc, s[1], ba.y);
    o0.z = fmaf(sc, s[2], ba.z);
    o0.w = fmaf(sc, s[3], ba.w);
    o1.x = fmaf(sc, s[4], bbv.x);
    o1.y = fmaf(sc, s[5], bbv.y);
    o1.z = fmaf(sc, s[6], bbv.z);
    o1.w = fmaf(sc, s[7], bbv.w);
    float4* op = (float4*)(out + (size_t)d * 64 + hl * 8);
    op[0] = o0;
    op[1] = o1;
}

// ---------------- launch ----------------
extern "C" void kernel_launch(void* const* d_in, const int* in_sizes, int n_in,
                              void* d_out, int out_size)
{
    const float* x  = (const float*)d_in[0];
    const int*   ei = (const int*)d_in[1];     // int32 (JAX coerces int64->int32)
    const float* W1 = (const float*)d_in[2];
    const float* b1 = (const float*)d_in[3];
    const float* W2 = (const float*)d_in[4];
    const float* b2 = (const float*)d_in[5];
    float* out = (float*)d_out;

    int n = in_sizes[0] / 128;   // 100000
    int E = in_sizes[1] / 2;     // 1600000
    const int* src = ei;
    const int* dst = ei + E;
    int nb = (n + SCAN_B - 1) / SCAN_B;

    constexpr int SM1 = 69632;
    constexpr int SM2 = 53248;
    cudaFuncSetAttribute(wmma_gemm_kernel<128, true, false>, cudaFuncAttributeMaxDynamicSharedMemorySize, SM1);
    cudaFuncSetAttribute(wmma_gemm_kernel<64, false, true>,  cudaFuncAttributeMaxDynamicSharedMemorySize, SM2);

    static cudaStream_t s2 = nullptr;
    static cudaEvent_t evF = nullptr, evJ = nullptr;
    if (s2 == nullptr) {
        cudaStreamCreateWithFlags(&s2, cudaStreamNonBlocking);
        cudaEventCreateWithFlags(&evF, cudaEventDisableTiming);
        cudaEventCreateWithFlags(&evJ, cudaEventDisableTiming);
    }

    // ---- fork at entry: s2 = convert_x -> GEMM1 (no dinv dependency!) ----
    cudaEventRecord(evF, 0);
    cudaStreamWaitEvent(s2, evF, 0);
    {
        int total8 = n * 16;
        convert_x_kernel<<<(total8 + 255) / 256, 256, 0, s2>>>(x, total8);
    }
    wmma_gemm_kernel<128, true, false><<<(n + 127) / 128, 512, SM1, s2>>>(W1, n);
    cudaEventRecord(evJ, s2);

    // ---- main: degree + dinv + CSR build (fully overlapped with s2) ----
    deg_init_kernel <<<(n + 255) / 256, 256>>>(n);
    {
        int t4 = (E + 3) / 4;
        deg_count_kernel<<<(t4 + 255) / 256, 256>>>(dst, E);
    }
    dinv_kernel<<<(n + 255) / 256, 256>>>(n);
    scan1_kernel<<<nb, SCAN_B>>>(n);
    scan2_kernel<<<1, 128>>>(nb, n);
    scan3_kernel<<<nb, SCAN_B>>>(n);
    fill_kernel <<<(E + 255) / 256, 256>>>(src, dst, E);

    // ---- join ----
    cudaStreamWaitEvent(0, evJ, 0);

    // layer 1 aggregation (applies dinv[s] per edge + dinv[d] + relu)
    {
        int warps = (n + 1) / 2;
        agg1_kernel<<<(warps * 32 + 255) / 256, 256>>>(b1, n);
    }

    // layer 2
    wmma_gemm_kernel<64, false, true><<<(n + 127) / 128, 512, SM2>>>(W2, n);
    {
        int warps = (n + 3) / 4;
        agg2_kernel<<<(warps * 32 + 255) / 256, 256>>>(b2, out, n);
    }
}